// round 15
// baseline (speedup 1.0000x reference)
#include <cuda_runtime.h>
#include <cuda_fp16.h>
#include <cstdint>

// Problem dims
#define BZc   8
#define NUMc  1024
#define NAc   64
#define FDc   128
#define GRPS  4          // (b,p) groups per CTA

typedef unsigned int u32;
typedef unsigned long long u64;

// ---------------- helpers ----------------
__device__ __forceinline__ float tanha(float x) {           // HW approx
    float y; asm("tanh.approx.f32 %0, %1;" : "=f"(y) : "f"(x)); return y;
}
// Fast precise tanh: ex2 + rcp + 1 Newton step (~4e-7). Final logit only.
__device__ __forceinline__ float tanhp(float x) {
    float t; asm("ex2.approx.f32 %0, %1;" : "=f"(t) : "f"(x * 2.8853900817779268f));
    float d = 1.0f + t;
    float r; asm("rcp.approx.f32 %0, %1;" : "=f"(r) : "f"(d));
    r = fmaf(fmaf(-d, r, 1.0f), r, r);
    return fmaf(-2.0f, r, 1.0f);
}
__device__ __forceinline__ u32 pkh2(float a, float b) {
    __half2 h = __floats2half2_rn(a, b);
    return *(u32*)&h;
}
__device__ __forceinline__ u64 pk2(float a, float b) {
    u64 r; asm("mov.b64 %0, {%1,%2};" : "=l"(r) : "f"(a), "f"(b)); return r;
}
__device__ __forceinline__ void upk2(u64 v, float& a, float& b) {
    asm("mov.b64 {%0,%1}, %2;" : "=f"(a), "=f"(b) : "l"(v));
}
__device__ __forceinline__ u64 ffma2(u64 a, u64 b, u64 c) {
    u64 d; asm("fma.rn.f32x2 %0, %1, %2, %3;" : "=l"(d) : "l"(a), "l"(b), "l"(c)); return d;
}
__device__ __forceinline__ void mma_f16(float d[4],
    u32 a0, u32 a1, u32 a2, u32 a3, u32 b0, u32 b1)
{
    asm("mma.sync.aligned.m16n8k16.row.col.f32.f16.f16.f32 "
        "{%0,%1,%2,%3}, {%4,%5,%6,%7}, {%8,%9}, {%0,%1,%2,%3};"
        : "+f"(d[0]), "+f"(d[1]), "+f"(d[2]), "+f"(d[3])
        : "r"(a0), "r"(a1), "r"(a2), "r"(a3), "r"(b0), "r"(b1));
}
__device__ __forceinline__ void cpa16(u32 dst, const void* src) {
    asm volatile("cp.async.cg.shared.global [%0], [%1], 16;" :: "r"(dst), "l"(src));
}
#define CP_COMMIT() asm volatile("cp.async.commit_group;")
#define CP_WAIT0()  asm volatile("cp.async.wait_group 0;")

// ---------------- folded weight storage (fp16 fragment layouts) ----------------
__device__ uint4 g_WhF[4 * 8 * 32];   // A1 frags [tile(4)][kk(8)][lane(32)]
__device__ uint4 g_M2hF[2 * 5 * 32];  // M2 frags [m(2)][kk2(5)][lane(32)]
__device__ float g_c1[64];
__device__ float g_ca[32];
__device__ float g_B1[8][4];
__device__ float g_d1[8];
__device__ u64   g_B2p[8][8];         // packed output-pairs of folded Ws2
__device__ u64   g_d2p[8];            // packed bias pairs
__device__ float g_Wa2[32];
__device__ float g_ba2s;

// ---------------- weight folding kernel (multi-block grid-stride) ----------------
__global__ void disarm_prep(
    const float* __restrict__ Wf1, const float* __restrict__ bf1,
    const float* __restrict__ gf1, const float* __restrict__ btf1,
    const float* __restrict__ Wf2, const float* __restrict__ bf2,
    const float* __restrict__ Ws1, const float* __restrict__ bs1,
    const float* __restrict__ gs1, const float* __restrict__ bts1,
    const float* __restrict__ Ws2, const float* __restrict__ bs2,
    const float* __restrict__ gs2, const float* __restrict__ bts2,
    const float* __restrict__ Ws3, const float* __restrict__ bs3,
    const float* __restrict__ Wa1, const float* __restrict__ ba1,
    const float* __restrict__ ga1, const float* __restrict__ bta1,
    const float* __restrict__ Wa2, const float* __restrict__ ba2)
{
    const float inv = rsqrtf(1.0f + 1e-5f);
    const int t  = threadIdx.x + blockIdx.x * blockDim.x;
    const int nt = blockDim.x * gridDim.x;
    const int lt = threadIdx.x;

    auto wt = [&](int r, int c) -> float {
        return gf1[r] * inv * Wf1[r * FDc + c];
    };
    for (int i = t; i < 4 * 8 * 32; i += nt) {
        int tile = i >> 8, kk = (i >> 5) & 7, lane = i & 31;
        int g8 = lane >> 2, t4 = lane & 3;
        int r = 16 * tile + g8, c = 16 * kk + 2 * t4;
        uint4 v;
        v.x = pkh2(wt(r,     c), wt(r,     c + 1));
        v.y = pkh2(wt(r + 8, c), wt(r + 8, c + 1));
        v.z = pkh2(wt(r,     c + 8), wt(r,     c + 9));
        v.w = pkh2(wt(r + 8, c + 8), wt(r + 8, c + 9));
        g_WhF[i] = v;
    }
    auto m2 = [&](int o, int kk) -> float {
        float acc = 0.0f;
        if (kk < 64) {
            for (int j = 0; j < 32; ++j) acc += Wa1[o*64 + 32 + j] * Wf2[j*64 + kk];
        } else {
            for (int mq = 0; mq < 32; ++mq) acc += Wa1[o*64 + mq] * Ws3[mq*16 + (kk - 64)];
        }
        return ga1[o] * inv * acc;
    };
    // k-pair unit map: pair p<32 -> hidden rows (16(p>>3)+(p&7)), +8;
    //                  p>=32 -> spatial units 2(p-32), +1
    auto U = [&](int p, int e) -> int {
        if (p < 32) return 16 * (p >> 3) + (p & 7) + 8 * e;
        return 64 + 2 * (p - 32) + e;
    };
    for (int i = t; i < 2 * 5 * 32; i += nt) {
        int m = i / (5 * 32), kk2 = (i / 32) % 5, lane = i & 31;
        int g8 = lane >> 2, t4 = lane & 3;
        int r = 16 * m + g8;
        int p = 8 * kk2 + t4;
        uint4 v;
        v.x = pkh2(m2(r,     U(p, 0)),     m2(r,     U(p, 1)));
        v.y = pkh2(m2(r + 8, U(p, 0)),     m2(r + 8, U(p, 1)));
        v.z = pkh2(m2(r,     U(p + 4, 0)), m2(r,     U(p + 4, 1)));
        v.w = pkh2(m2(r + 8, U(p + 4, 0)), m2(r + 8, U(p + 4, 1)));
        g_M2hF[i] = v;
    }
    if (blockIdx.x == 0) {
        for (int i = lt; i < 64; i += blockDim.x) g_c1[i] = gf1[i]*inv*bf1[i] + btf1[i];
        if (lt < 32) {
            float acc = 0.0f;
            for (int j = 0; j < 32; ++j) acc += Wa1[lt*64 + 32 + j] * bf2[j];
            for (int mq = 0; mq < 32; ++mq) acc += Wa1[lt*64 + mq] * bs3[mq];
            g_ca[lt] = ga1[lt]*inv*(acc + ba1[lt]) + bta1[lt];
        }
        if (lt < 8) {
            for (int i = 0; i < 3; ++i) g_B1[lt][i] = gs1[lt]*inv*Ws1[lt*3 + i];
            g_B1[lt][3] = 0.0f;
            g_d1[lt] = gs1[lt]*inv*bs1[lt] + bts1[lt];
        }
        if (lt < 64) {   // packed spatial layer-2: output pair (2j, 2j+1), input i
            int j = lt >> 3, i = lt & 7;
            float a = gs2[2*j]   * inv * Ws2[(2*j)  * 8 + i];
            float b = gs2[2*j+1] * inv * Ws2[(2*j+1)* 8 + i];
            g_B2p[j][i] = pk2(a, b);
        }
        if (lt < 8) {
            float a = gs2[2*lt]   * inv * bs2[2*lt]   + bts2[2*lt];
            float b = gs2[2*lt+1] * inv * bs2[2*lt+1] + bts2[2*lt+1];
            g_d2p[lt] = pk2(a, b);
        }
        if (lt < 32) g_Wa2[lt] = Wa2[lt];
        if (lt == 0) g_ba2s = ba2[0];
    }
}

// ---------------- smem layout (bytes) ----------------
#define XHS      72                         // u32 per channel-pair row (fp16 X, SINGLE buffer)
#define SGS      68                         // f32 per channel row (cp.async stage)
#define CHS      72
#define SPS      72
#define SM_XH    0                          // 64*72*4 = 18432
#define SM_STG   18432                      // 128*68*4 = 34816
#define SM_CH    (SM_STG + 34816)           // 32*72*4 = 9216
#define SM_SP    (SM_CH + 9216)             // 4*8*72*4 = 9216
#define SM_PART  (SM_SP + 9216)             // 1024
#define SM_C1    (SM_PART + 1024)           // 256
#define SM_CA    (SM_C1 + 256)              // 128
#define SM_WA2   (SM_CA + 128)              // 128
#define SM_B1    (SM_WA2 + 128)             // 128
#define SM_D1    (SM_B1 + 128)              // 32
#define SM_B2P   (SM_D1 + 32)               // 512
#define SM_D2P   (SM_B2P + 512)             // 64
#define SM_BA2   (SM_D2P + 64)              // 16
#define SM_TOTAL (SM_BA2 + 16)              // ~74 KB -> 3 CTAs/SM = 222 KB

// ---------------- main fused kernel ----------------
// R14 body, 3-CTA occupancy: q-prefetch regs -> cp.async f32 stage (self-
// produced/self-consumed per thread, wait_group 0, no extra barrier); M2
// frags reloaded per group (L1-hit LDG.128). XH single-buffered: converted
// post-SYNC1 (all mma1 reads done), published by SYNC2. 2 syncs/group kept.
__global__ void __launch_bounds__(256, 3) disarm_mma(
    const float* __restrict__ loc, const float* __restrict__ feat,
    float* __restrict__ out)
{
    extern __shared__ char smem[];
    u32*   sXH  = (u32*)(smem + SM_XH);
    float* sSTG = (float*)(smem + SM_STG);
    u32*   sCH  = (u32*)(smem + SM_CH);
    u32*   sSP  = (u32*)(smem + SM_SP);
    float (*sPart)[2][64] = (float (*)[2][64])(smem + SM_PART);  // [buf][m][a]
    float* sc1   = (float*)(smem + SM_C1);
    float* sca   = (float*)(smem + SM_CA);
    float* sWa2v = (float*)(smem + SM_WA2);
    float (*sB1)[4] = (float (*)[4])(smem + SM_B1);
    float* sd1   = (float*)(smem + SM_D1);
    u64* sB2p    = (u64*)(smem + SM_B2P);
    u64* sd2p    = (u64*)(smem + SM_D2P);
    float* sba2  = (float*)(smem + SM_BA2);

    u32 sbase;
    asm("{.reg .u64 t; cvta.to.shared.u64 t, %1; cvt.u32.u64 %0, t;}"
        : "=r"(sbase) : "l"(smem));

    const int tid  = threadIdx.x;
    const int warp = tid >> 5;
    const int lane = tid & 31;
    const int g8   = lane >> 2;
    const int t4   = lane & 3;
    const int wM   = warp >> 1;   // mma1 row tile (0..3)
    const int wN   = warp & 1;    // mma1 anchor half (0..1)
    const int m    = warp & 1;    // mma2 row half
    const int nt   = warp >> 1;   // mma2 anchor 16-col tile

    const size_t cs = (size_t)NUMc * NAc;
    const int gp0 = blockIdx.x * GRPS;

    // X-staging indices
    const int cp0 = tid >> 4;      // channel-pair base; iter it uses cp0 + 16*it
    const int ab  = tid & 15;      // anchor float4-block

    // issue cp.async for group 0's X (raw f32) into stage
    {
        const int b = gp0 >> 10, p = gp0 & 1023;
        const float* fb = feat + (size_t)b * FDc * cs + (size_t)p * NAc;
        #pragma unroll
        for (int it = 0; it < 4; ++it) {
            const int cp = cp0 + 16 * it;
            cpa16(sbase + SM_STG + ((2*cp    ) * SGS + 4*ab) * 4, fb + (size_t)(2*cp  ) * cs + 4*ab);
            cpa16(sbase + SM_STG + ((2*cp + 1) * SGS + 4*ab) * 4, fb + (size_t)(2*cp+1) * cs + 4*ab);
        }
        CP_COMMIT();
    }

    // ---- persistent A1 fragments (8 coalesced LDG.128) ----
    u32 A[32];
    {
        const uint4* aw = g_WhF + (size_t)wM * 8 * 32 + lane;
        #pragma unroll
        for (int kk = 0; kk < 8; ++kk) {
            uint4 v = __ldg(aw + kk * 32);
            A[4*kk+0] = v.x; A[4*kk+1] = v.y; A[4*kk+2] = v.z; A[4*kk+3] = v.w;
        }
    }

    // ---- stage small weights ----
    if (tid < 64) sc1[tid] = g_c1[tid];
    if (tid < 32) { sca[tid] = g_ca[tid]; sWa2v[tid] = g_Wa2[tid]; }
    if (tid < 32) sB1[tid>>2][tid&3] = g_B1[tid>>2][tid&3];
    if (tid < 8)  sd1[tid] = g_d1[tid];
    if (tid >= 128 && tid < 192) sB2p[tid-128] = g_B2p[(tid-128)>>3][(tid-128)&7];
    if (tid >= 192 && tid < 200) sd2p[tid-192] = g_d2p[tid-192];
    if (tid == 0) sba2[0] = g_ba2s;
    __syncthreads();   // weights visible (needed by spatial below)

    // ---- prologue: spatial branch for ALL 4 groups (1 instance/thread) ----
    {
        const int gi  = tid >> 6;           // group 0..3
        const int a   = tid & 63;           // anchor
        const int gp  = gp0 + gi;
        const int b   = gp >> 10;
        const int p   = gp & 1023;
        const float* lp = loc + (((size_t)(b*NUMc + p))*NAc + a) * 3;
        const float l0 = __ldg(lp), l1 = __ldg(lp + 1), l2 = __ldg(lp + 2);

        u64 sv[8];
        #pragma unroll
        for (int j = 0; j < 8; ++j) {
            float s = tanha(sB1[j][0]*l0 + sB1[j][1]*l1 + sB1[j][2]*l2 + sd1[j]);
            sv[j] = pk2(s, s);
        }
        u32* dst = sSP + (gi * 8) * SPS + a;
        #pragma unroll
        for (int j = 0; j < 8; ++j) {
            u64 acc = sd2p[j];
            #pragma unroll
            for (int i = 0; i < 8; ++i) acc = ffma2(sB2p[j*8 + i], sv[i], acc);
            float ta, tb; upk2(acc, ta, tb);
            dst[j * SPS] = pkh2(tanha(ta), tanha(tb));
        }
    }

    // ---- convert stage -> XH for group 0 (own cp.async bytes) ----
    CP_WAIT0();
    #pragma unroll
    for (int it = 0; it < 4; ++it) {
        const int cp = cp0 + 16 * it;
        const float4 xa = *(const float4*)(sSTG + (2*cp    ) * SGS + 4*ab);
        const float4 xc = *(const float4*)(sSTG + (2*cp + 1) * SGS + 4*ab);
        uint4 w;
        w.x = pkh2(xa.x, xc.x); w.y = pkh2(xa.y, xc.y);
        w.z = pkh2(xa.z, xc.z); w.w = pkh2(xa.w, xc.w);
        *(uint4*)(sXH + cp * XHS + 4 * ab) = w;
    }
    __syncthreads();   // sSP + XH(group 0) published

    #pragma unroll 1
    for (int g = 0; g < GRPS; ++g) {
        const int gp = gp0 + g;

        // ---- mma1: 32 fp16 mma/warp, 2 LDS.128 per kstep ----
        float D[4][4];
        #pragma unroll
        for (int n = 0; n < 4; ++n) { D[n][0]=0.f; D[n][1]=0.f; D[n][2]=0.f; D[n][3]=0.f; }
        #pragma unroll
        for (int kk = 0; kk < 8; ++kk) {
            const uint4 v0 = *(const uint4*)(sXH + (8*kk + t4    ) * XHS + 32*wN + 4*g8);
            const uint4 v1 = *(const uint4*)(sXH + (8*kk + t4 + 4) * XHS + 32*wN + 4*g8);
            mma_f16(D[0], A[4*kk], A[4*kk+1], A[4*kk+2], A[4*kk+3], v0.x, v1.x);
            mma_f16(D[1], A[4*kk], A[4*kk+1], A[4*kk+2], A[4*kk+3], v0.y, v1.y);
            mma_f16(D[2], A[4*kk], A[4*kk+1], A[4*kk+2], A[4*kk+3], v0.z, v1.z);
            mma_f16(D[3], A[4*kk], A[4*kk+1], A[4*kk+2], A[4*kk+3], v0.w, v1.w);
        }

        // ---- issue cp.async for group g+1's X (no registers held) ----
        if (g + 1 < GRPS) {
            const int gp1 = gp + 1;
            const int b1 = gp1 >> 10, p1 = gp1 & 1023;
            const float* fb1 = feat + (size_t)b1 * FDc * cs + (size_t)p1 * NAc;
            #pragma unroll
            for (int it = 0; it < 4; ++it) {
                const int cp = cp0 + 16 * it;
                cpa16(sbase + SM_STG + ((2*cp    ) * SGS + 4*ab) * 4, fb1 + (size_t)(2*cp  ) * cs + 4*ab);
                cpa16(sbase + SM_STG + ((2*cp + 1) * SGS + 4*ab) * 4, fb1 + (size_t)(2*cp+1) * cs + 4*ab);
            }
            CP_COMMIT();
        }

        // ---- epi1: tanh(H + c1) -> C k-pairs 0..31 (2 STS.128) ----
        {
            const int pp = 8*wM + g8;
            const float c1a = sc1[16*wM + g8];
            const float c1b = sc1[16*wM + g8 + 8];
            u32* cw = sCH + pp * CHS + 32*wN + 8*t4;
            uint4 w;
            w.x = pkh2(tanha(D[0][0] + c1a), tanha(D[0][2] + c1b));
            w.y = pkh2(tanha(D[1][0] + c1a), tanha(D[1][2] + c1b));
            w.z = pkh2(tanha(D[2][0] + c1a), tanha(D[2][2] + c1b));
            w.w = pkh2(tanha(D[3][0] + c1a), tanha(D[3][2] + c1b));
            *(uint4*)cw = w;
            w.x = pkh2(tanha(D[0][1] + c1a), tanha(D[0][3] + c1b));
            w.y = pkh2(tanha(D[1][1] + c1a), tanha(D[1][3] + c1b));
            w.z = pkh2(tanha(D[2][1] + c1a), tanha(D[2][3] + c1b));
            w.w = pkh2(tanha(D[3][1] + c1a), tanha(D[3][3] + c1b));
            *(uint4*)(cw + 4) = w;
        }
        __syncthreads();   // SYNC1: sC ready; all mma1 XH reads done

        // ---- mma2: 10 fp16 mma/warp; M2 frags via L1-hit LDG.128 ----
        float D2[2][4];
        D2[0][0]=0.f; D2[0][1]=0.f; D2[0][2]=0.f; D2[0][3]=0.f;
        D2[1][0]=0.f; D2[1][1]=0.f; D2[1][2]=0.f; D2[1][3]=0.f;
        {
            const uint4* mw = g_M2hF + (size_t)m * 5 * 32 + lane;
            #pragma unroll
            for (int kk2 = 0; kk2 < 4; ++kk2) {
                const uint4 mv = __ldg(mw + kk2 * 32);
                const uint2 w0 = *(const uint2*)(sCH + (8*kk2 + t4    ) * CHS + 16*nt + 2*g8);
                const uint2 w1 = *(const uint2*)(sCH + (8*kk2 + t4 + 4) * CHS + 16*nt + 2*g8);
                mma_f16(D2[0], mv.x, mv.y, mv.z, mv.w, w0.x, w1.x);
                mma_f16(D2[1], mv.x, mv.y, mv.z, mv.w, w0.y, w1.y);
            }
            {   // kk2 = 4: spatial rows from sSP[g]
                const uint4 mv = __ldg(mw + 4 * 32);
                const u32* sp = sSP + (g * 8) * SPS + 16*nt + 2*g8;
                const uint2 w0 = *(const uint2*)(sp + t4 * SPS);
                const uint2 w1 = *(const uint2*)(sp + (t4 + 4) * SPS);
                mma_f16(D2[0], mv.x, mv.y, mv.z, mv.w, w0.x, w1.x);
                mma_f16(D2[1], mv.x, mv.y, mv.z, mv.w, w0.y, w1.y);
            }
        }

        // ---- epi2: head partials (HW tanh) ----
        {
            const int ro = 16*m + g8;
            const float wa  = sWa2v[ro],   wb  = sWa2v[ro + 8];
            const float caa = sca[ro],     cab = sca[ro + 8];
            float p0 = wa * tanha(D2[0][0] + caa) + wb * tanha(D2[0][2] + cab); // +0
            float p2 = wa * tanha(D2[1][0] + caa) + wb * tanha(D2[1][2] + cab); // +1
            float p1 = wa * tanha(D2[0][1] + caa) + wb * tanha(D2[0][3] + cab); // +2
            float p3 = wa * tanha(D2[1][1] + caa) + wb * tanha(D2[1][3] + cab); // +3
            const unsigned m32 = 0xffffffffu;
            #pragma unroll
            for (int off = 4; off <= 16; off <<= 1) {
                p0 += __shfl_xor_sync(m32, p0, off);
                p1 += __shfl_xor_sync(m32, p1, off);
                p2 += __shfl_xor_sync(m32, p2, off);
                p3 += __shfl_xor_sync(m32, p3, off);
            }
            if (g8 == 0) {
                float4 v; v.x = p0; v.y = p2; v.z = p1; v.w = p3;
                *(float4*)&sPart[g & 1][m][16*nt + 4*t4] = v;
            }
        }

        // ---- convert stage -> XH for group g+1 (post-SYNC1: XH reads done) ----
        if (g + 1 < GRPS) {
            CP_WAIT0();
            #pragma unroll
            for (int it = 0; it < 4; ++it) {
                const int cp = cp0 + 16 * it;
                const float4 xa = *(const float4*)(sSTG + (2*cp    ) * SGS + 4*ab);
                const float4 xc = *(const float4*)(sSTG + (2*cp + 1) * SGS + 4*ab);
                uint4 w;
                w.x = pkh2(xa.x, xc.x); w.y = pkh2(xa.y, xc.y);
                w.z = pkh2(xa.z, xc.z); w.w = pkh2(xa.w, xc.w);
                *(uint4*)(sXH + cp * XHS + 4 * ab) = w;
            }
        }
        __syncthreads();   // SYNC2: sPart + XH(g+1) visible; sC/sSP reads done

        // ---- tail: warp 0 softmax + min-max norm (overlaps next mma1) ----
        if (warp == 0) {
            const int a0 = lane, a1 = lane + 32;
            const float* pb0 = sPart[g & 1][0];
            const float* pb1 = sPart[g & 1][1];
            const float lg0 = tanhp(pb0[a0] + pb1[a0] + sba2[0]);
            const float lg1 = tanhp(pb0[a1] + pb1[a1] + sba2[0]);

            const unsigned m32 = 0xffffffffu;
            float mx = fmaxf(lg0, lg1);
            float mn = fminf(lg0, lg1);
            #pragma unroll
            for (int off = 16; off > 0; off >>= 1) {
                mx = fmaxf(mx, __shfl_xor_sync(m32, mx, off));
                mn = fminf(mn, __shfl_xor_sync(m32, mn, off));
            }
            const float e0 = expf(lg0 - mx);
            const float e1 = expf(lg1 - mx);
            float ssum = e0 + e1;
            #pragma unroll
            for (int off = 16; off > 0; off >>= 1) ssum += __shfl_xor_sync(m32, ssum, off);
            const float invs = 1.0f / ssum;

            const float w0  = e0 * invs;
            const float w1  = e1 * invs;
            const float wmn = expf(mn - mx) * invs;
            const float wmx = invs;
            const float kk  = (1.0f + 1e-6f) / (wmx - wmn + 1e-6f);

            float* ob = out + (size_t)gp * NAc;
            float* on = ob + (size_t)BZc * NUMc * NAc;
            ob[a0] = w0;
            ob[a1] = w1;
            on[a0] = kk * (w0 - wmn);
            on[a1] = kk * (w1 - wmn);
        }
    }
}

// ---------------- launch ----------------
extern "C" void kernel_launch(void* const* d_in, const int* in_sizes, int n_in,
                              void* d_out, int out_size)
{
    const float* loc  = (const float*)d_in[0];
    const float* feat = (const float*)d_in[1];

    disarm_prep<<<16, 256>>>(
        (const float*)d_in[2],  (const float*)d_in[3],  (const float*)d_in[4],  (const float*)d_in[5],
        (const float*)d_in[6],  (const float*)d_in[7],
        (const float*)d_in[8],  (const float*)d_in[9],  (const float*)d_in[10], (const float*)d_in[11],
        (const float*)d_in[12], (const float*)d_in[13], (const float*)d_in[14], (const float*)d_in[15],
        (const float*)d_in[16], (const float*)d_in[17],
        (const float*)d_in[18], (const float*)d_in[19], (const float*)d_in[20], (const float*)d_in[21],
        (const float*)d_in[22], (const float*)d_in[23]);

    static int smem_set = 0;
    if (!smem_set) {
        cudaFuncSetAttribute(disarm_mma,
                             cudaFuncAttributeMaxDynamicSharedMemorySize, SM_TOTAL);
        cudaFuncSetAttribute(disarm_mma,
                             cudaFuncAttributePreferredSharedMemoryCarveout, 100);
        smem_set = 1;
    }
    disarm_mma<<<(BZc * NUMc) / GRPS, 256, SM_TOTAL>>>(loc, feat, (float*)d_out);
}